// round 10
// baseline (speedup 1.0000x reference)
#include <cuda_runtime.h>
#include <cstdint>
#include <math.h>

// ---------------------------------------------------------------------------
// Problem dims
// ---------------------------------------------------------------------------
#define NB   8
#define CC   1024
#define TT   16
#define HH   14
#define WW   14
#define DD   512
#define THW  (TT*HH*WW)   // 3136
#define PH   (HH/2)
#define PW   (WW/2)
#define PP   (TT*PH*PW)   // 784

// Scratch (all K-contiguous layouts; all GEMM inputs pre-rounded to tf32)
__device__ float g_xT    [NB*THW*CC];
__device__ float g_xpT   [NB*PP*CC];
__device__ float g_thetaT[NB*THW*DD];
__device__ float g_phiT  [NB*PP*DD];
__device__ float g_g     [NB*DD*PP];
__device__ float g_attn  [NB*THW*PP];
__device__ float g_oT    [NB*THW*DD];
__device__ float g_wth   [DD*CC];
__device__ float g_wph   [DD*CC];
__device__ float g_wg    [DD*CC];
__device__ float g_wout  [CC*DD];

// ---------------------------------------------------------------------------
// Tile geometry: 128x128 CTA tile, BK=32, 256 threads (8 warps, 64x32 each)
// 3-stage cp.async pipeline.
// ---------------------------------------------------------------------------
#define BM  128
#define BN  128
#define BK  32
#define NT  256
#define NSTAGE 3
#define PAD 4
#define LDT (BK + PAD)          // 36 floats = 144 B per row (16B-aligned)
#define TILE_FLOATS ((BM + BN) * LDT)
#define SMEM_BYTES  (NSTAGE * TILE_FLOATS * 4)   // 110592 B

// ---------------------------------------------------------------------------
// PTX helpers
// ---------------------------------------------------------------------------
__device__ __forceinline__ uint32_t tf32r(float f) {
    uint32_t u;
    asm("cvt.rna.tf32.f32 %0, %1;" : "=r"(u) : "f"(f));
    return u;
}
__device__ __forceinline__ float tf32f(float f) { return __uint_as_float(tf32r(f)); }
__device__ __forceinline__ uint32_t smem_u32(const void* p) {
    uint32_t a;
    asm("{ .reg .u64 t; cvta.to.shared.u64 t, %1; cvt.u32.u64 %0, t; }" : "=r"(a) : "l"(p));
    return a;
}
__device__ __forceinline__ void cp16(uint32_t dst, const void* src, bool pred) {
    int sz = pred ? 16 : 0;
    asm volatile("cp.async.ca.shared.global [%0], [%1], 16, %2;"
                 :: "r"(dst), "l"(src), "r"(sz));
}
#define CP_COMMIT() asm volatile("cp.async.commit_group;" ::: "memory")
template<int N> __device__ __forceinline__ void cp_wait() {
    asm volatile("cp.async.wait_group %0;" :: "n"(N) : "memory");
}
__device__ __forceinline__ void mma8(float* c, const uint32_t* a, const uint32_t* b) {
    asm volatile(
        "mma.sync.aligned.m16n8k8.row.col.f32.tf32.tf32.f32 "
        "{%0,%1,%2,%3}, {%4,%5,%6,%7}, {%8,%9}, {%0,%1,%2,%3};"
        : "+f"(c[0]), "+f"(c[1]), "+f"(c[2]), "+f"(c[3])
        : "r"(a[0]), "r"(a[1]), "r"(a[2]), "r"(a[3]), "r"(b[0]), "r"(b[1]));
}
__device__ __forceinline__ void ldsm4(uint32_t* r, uint32_t addr) {
    asm volatile("ldmatrix.sync.aligned.m8n8.x4.shared.b16 {%0,%1,%2,%3}, [%4];"
                 : "=r"(r[0]), "=r"(r[1]), "=r"(r[2]), "=r"(r[3]) : "r"(addr));
}

// K-contiguous staging: elem(r,k)=src[r*ld+k], cp.async 16B, zfill OOB.
__device__ __forceinline__ void stage_kc(const float* __restrict__ src, uint32_t tile_u,
                                         int rows, int k0, int K, long long ld, int tid) {
    #pragma unroll
    for (int i = 0; i < 4; i++) {
        int idx = tid + i * NT;
        int r   = idx >> 3;
        int c4  = (idx & 7) * 4;
        bool ok = (r < rows) && (k0 + c4 < K);
        const float* s = ok ? (src + (long long)r * ld + k0 + c4) : src;
        cp16(tile_u + (uint32_t)(r * LDT + c4) * 4u, s, ok);
    }
}

// ---------------------------------------------------------------------------
// tf32 mma.sync GEMM (ldmatrix fragments): C[M,N] = alpha * A·B^T, both KC.
// 8 warps, 64x32 warp tile, 3-stage cp.async pipeline.
// RND: round outputs to tf32. EPI: residual+affine.
// ---------------------------------------------------------------------------
template<bool EPI, bool RND>
__global__ __launch_bounds__(NT, 2)
void mma_gemm(const float* __restrict__ A, const float* __restrict__ B,
              float* __restrict__ C, int M, int N, int K,
              long long ldA, long long ldB, long long ldC,
              long long sA, long long sB, long long sC, float alpha,
              const float* __restrict__ scale, const float* __restrict__ bias,
              const float* __restrict__ resid, long long sR) {
    extern __shared__ float smem[];
    const int tid  = threadIdx.x;
    const int wid  = tid >> 5;
    const int lane = tid & 31;
    const int bz = blockIdx.z;
    const int bm = blockIdx.y * BM;
    const int bn = blockIdx.x * BN;

    A += (long long)bz * sA;
    B += (long long)bz * sB;
    C += (long long)bz * sC;

    const int rowsA = min(BM, M - bm);
    const int rowsB = min(BN, N - bn);
    const float* srcA = A + (long long)bm * ldA;
    const float* srcB = B + (long long)bn * ldB;

    const uint32_t smb = smem_u32(smem);
    uint32_t uA[NSTAGE], uB[NSTAGE];
    #pragma unroll
    for (int s = 0; s < NSTAGE; s++) {
        uA[s] = smb + (uint32_t)(s * TILE_FLOATS) * 4u;
        uB[s] = uA[s] + (uint32_t)(BM * LDT) * 4u;
    }

    const int wm = (wid >> 2) * 64;
    const int wn = (wid & 3) * 32;

    // ldmatrix per-lane offsets (bytes)
    const int lrow = lane & 7, grp = lane >> 3;
    const uint32_t aoff = ((lrow + (grp & 1) * 8) * LDT + (grp >> 1) * 4) * 4u;
    const uint32_t boff = ((lrow + (grp >> 1) * 8) * LDT + (grp & 1) * 4) * 4u;

    float acc[4][4][4];
    #pragma unroll
    for (int i = 0; i < 4; i++)
        #pragma unroll
        for (int j = 0; j < 4; j++)
            #pragma unroll
            for (int e = 0; e < 4; e++) acc[i][j][e] = 0.f;

    const int KT = (K + BK - 1) / BK;

    // prologue: stages 0 and 1 in flight
    stage_kc(srcA, uA[0], rowsA, 0, K, ldA, tid);
    stage_kc(srcB, uB[0], rowsB, 0, K, ldB, tid);
    CP_COMMIT();
    if (1 < KT) {
        stage_kc(srcA, uA[1], rowsA, BK, K, ldA, tid);
        stage_kc(srcB, uB[1], rowsB, BK, K, ldB, tid);
        CP_COMMIT();
        cp_wait<1>();
    } else {
        cp_wait<0>();
    }
    __syncthreads();

    int buf = 0;
    for (int kt = 0; kt < KT; kt++) {
        const bool pf = (kt + 2 < KT);
        if (pf) {
            const int nb = (buf + 2 >= NSTAGE) ? (buf + 2 - NSTAGE) : (buf + 2);
            const int k0 = (kt + 2) * BK;
            stage_kc(srcA, uA[nb], rowsA, k0, K, ldA, tid);
            stage_kc(srcB, uB[nb], rowsB, k0, K, ldB, tid);
            CP_COMMIT();
        }

        const uint32_t abase = uA[buf] + (uint32_t)(wm * LDT) * 4u + aoff;
        const uint32_t bbase = uB[buf] + (uint32_t)(wn * LDT) * 4u + boff;
        #pragma unroll
        for (int ks = 0; ks < 4; ks++) {
            const uint32_t ksb = (uint32_t)(ks * 8) * 4u;
            uint32_t afr[4][4], bfr[4][2];
            #pragma unroll
            for (int i = 0; i < 4; i++)
                ldsm4(afr[i], abase + (uint32_t)(i * 16 * LDT) * 4u + ksb);
            #pragma unroll
            for (int p = 0; p < 2; p++) {
                uint32_t bq[4];
                ldsm4(bq, bbase + (uint32_t)(p * 16 * LDT) * 4u + ksb);
                bfr[2 * p][0] = bq[0]; bfr[2 * p][1] = bq[1];
                bfr[2 * p + 1][0] = bq[2]; bfr[2 * p + 1][1] = bq[3];
            }
            #pragma unroll
            for (int i = 0; i < 4; i++)
                #pragma unroll
                for (int j = 0; j < 4; j++)
                    mma8(acc[i][j], afr[i], bfr[j]);
        }

        // ensure tile kt+1 landed; with a commit this iter (tiles kt+1, kt+2
        // pending) wait<1> completes kt+1; without, wait<0> closes the tail.
        if (pf) cp_wait<1>(); else cp_wait<0>();
        __syncthreads();
        buf = (buf + 1 == NSTAGE) ? 0 : buf + 1;
    }

    // epilogue
    #pragma unroll
    for (int i = 0; i < 4; i++) {
        const int r0 = bm + wm + i * 16 + (lane >> 2);
        #pragma unroll
        for (int j = 0; j < 4; j++) {
            const int c = bn + wn + j * 8 + 2 * (lane & 3);
            if (c >= N) continue;
            #pragma unroll
            for (int h = 0; h < 2; h++) {
                const int r = r0 + h * 8;
                if (r >= M) continue;
                const long long base = (long long)r * ldC + c;
                float2 o;
                if (EPI) {
                    const float sc = scale[r], bi = bias[r];
                    const float2 rr = *reinterpret_cast<const float2*>(
                        &resid[(long long)bz * sR + base]);
                    o.x = rr.x + fmaf(acc[i][j][2 * h + 0], sc, bi);
                    o.y = rr.y + fmaf(acc[i][j][2 * h + 1], sc, bi);
                } else {
                    o.x = alpha * acc[i][j][2 * h + 0];
                    o.y = alpha * acc[i][j][2 * h + 1];
                    if (RND) { o.x = tf32f(o.x); o.y = tf32f(o.y); }
                }
                *reinterpret_cast<float2*>(&C[base]) = o;
            }
        }
    }
}

// ---------------------------------------------------------------------------
// Fused weight rounding: all four weight arrays are 512*1024 elements.
// ---------------------------------------------------------------------------
#define WELEMS (DD*CC)
__global__ void round4_kernel(const float* __restrict__ s0, float* __restrict__ d0,
                              const float* __restrict__ s1, float* __restrict__ d1,
                              const float* __restrict__ s2, float* __restrict__ d2,
                              const float* __restrict__ s3, float* __restrict__ d3) {
    int gi = (blockIdx.x * blockDim.x + threadIdx.x) * 4;
    int arr = gi / WELEMS;
    int i   = gi % WELEMS;
    const float* src = (arr == 0) ? s0 : (arr == 1) ? s1 : (arr == 2) ? s2 : s3;
    float*       dst = (arr == 0) ? d0 : (arr == 1) ? d1 : (arr == 2) ? d2 : d3;
    float4 v = *reinterpret_cast<const float4*>(src + i);
    float4 o;
    o.x = tf32f(v.x); o.y = tf32f(v.y); o.z = tf32f(v.z); o.w = tf32f(v.w);
    *reinterpret_cast<float4*>(dst + i) = o;
}

// ---------------------------------------------------------------------------
// Tiled transpose + tf32 round: x [C, THW] -> xT [THW, C]
// ---------------------------------------------------------------------------
__global__ void transpose_kernel(const float* __restrict__ x, float* __restrict__ xT) {
    __shared__ float tile[32][33];
    const int bz = blockIdx.z;
    const float* src = x  + (long long)bz * CC * THW;
    float*       dst = xT + (long long)bz * THW * CC;
    const int t0 = blockIdx.x * 32;
    const int c0 = blockIdx.y * 32;
    #pragma unroll
    for (int j = threadIdx.y; j < 32; j += 8)
        tile[j][threadIdx.x] = tf32f(src[(long long)(c0 + j) * THW + t0 + threadIdx.x]);
    __syncthreads();
    #pragma unroll
    for (int j = threadIdx.y; j < 32; j += 8)
        dst[(long long)(t0 + j) * CC + c0 + threadIdx.x] = tile[threadIdx.x][j];
}

// ---------------------------------------------------------------------------
// Pooled transpose: xT [THW, C] -> xpT [PP, C]
// ---------------------------------------------------------------------------
__global__ void pooltrans_kernel(const float* __restrict__ xT, float* __restrict__ xpT) {
    const int p  = blockIdx.x;
    const int nb = blockIdx.y;
    const int t  = p / (PH * PW);
    const int ij = p % (PH * PW);
    const int i  = ij / PW;
    const int j  = ij % PW;
    const int r00 = t * (HH * WW) + (2 * i) * WW + 2 * j;
    const float4* s0 = (const float4*)(xT + ((long long)nb * THW + r00) * CC);
    const float4* s1 = s0 + CC / 4;
    const float4* s2 = (const float4*)(xT + ((long long)nb * THW + r00 + WW) * CC);
    const float4* s3 = s2 + CC / 4;
    float4* d = (float4*)(xpT + ((long long)nb * PP + p) * CC);
    const int c = threadIdx.x;
    float4 a = s0[c], b = s1[c], e = s2[c], f = s3[c];
    float4 o;
    o.x = fmaxf(fmaxf(a.x, b.x), fmaxf(e.x, f.x));
    o.y = fmaxf(fmaxf(a.y, b.y), fmaxf(e.y, f.y));
    o.z = fmaxf(fmaxf(a.z, b.z), fmaxf(e.z, f.z));
    o.w = fmaxf(fmaxf(a.w, b.w), fmaxf(e.w, f.w));
    d[c] = o;
}

// ---------------------------------------------------------------------------
// Warp-per-row softmax (cols = 784); output rounded to tf32
// ---------------------------------------------------------------------------
__global__ void softmax_kernel(float* __restrict__ data, int rows, int cols) {
    int warp = blockIdx.x * (blockDim.x >> 5) + (threadIdx.x >> 5);
    if (warp >= rows) return;
    int lane = threadIdx.x & 31;
    float* row = data + (long long)warp * cols;
    float vals[25];
    int cnt = 0;
    float mx = -INFINITY;
    for (int c = lane; c < cols; c += 32) {
        float v = row[c];
        vals[cnt++] = v;
        mx = fmaxf(mx, v);
    }
    #pragma unroll
    for (int o = 16; o; o >>= 1) mx = fmaxf(mx, __shfl_xor_sync(0xffffffffu, mx, o));
    float sum = 0.f;
    for (int i = 0; i < cnt; i++) { vals[i] = __expf(vals[i] - mx); sum += vals[i]; }
    #pragma unroll
    for (int o = 16; o; o >>= 1) sum += __shfl_xor_sync(0xffffffffu, sum, o);
    float inv = 1.0f / sum;
    cnt = 0;
    for (int c = lane; c < cols; c += 32) row[c] = tf32f(vals[cnt++] * inv);
}

// ---------------------------------------------------------------------------
// Launch
// ---------------------------------------------------------------------------
static inline dim3 g128(int M, int N, int b) {
    return dim3((N + BN - 1) / BN, (M + BM - 1) / BM, b);
}

extern "C" void kernel_launch(void* const* d_in, const int* in_sizes, int n_in,
                              void* d_out, int out_size) {
    const float* x       = (const float*)d_in[0];
    const float* w_theta = (const float*)d_in[1];
    const float* w_phi   = (const float*)d_in[2];
    const float* w_g     = (const float*)d_in[3];
    const float* w_out   = (const float*)d_in[4];
    const float* nscale  = (const float*)d_in[5];
    const float* nbias   = (const float*)d_in[6];
    float* out = (float*)d_out;

    float *xT, *xpT, *thetaT, *phiT, *gg, *attn, *oT, *wth, *wph, *wg, *wout;
    cudaGetSymbolAddress((void**)&xT,     g_xT);
    cudaGetSymbolAddress((void**)&xpT,    g_xpT);
    cudaGetSymbolAddress((void**)&thetaT, g_thetaT);
    cudaGetSymbolAddress((void**)&phiT,   g_phiT);
    cudaGetSymbolAddress((void**)&gg,     g_g);
    cudaGetSymbolAddress((void**)&attn,   g_attn);
    cudaGetSymbolAddress((void**)&oT,     g_oT);
    cudaGetSymbolAddress((void**)&wth,    g_wth);
    cudaGetSymbolAddress((void**)&wph,    g_wph);
    cudaGetSymbolAddress((void**)&wg,     g_wg);
    cudaGetSymbolAddress((void**)&wout,   g_wout);

    cudaFuncSetAttribute(mma_gemm<false, true >, cudaFuncAttributeMaxDynamicSharedMemorySize, SMEM_BYTES);
    cudaFuncSetAttribute(mma_gemm<false, false>, cudaFuncAttributeMaxDynamicSharedMemorySize, SMEM_BYTES);
    cudaFuncSetAttribute(mma_gemm<true,  false>, cudaFuncAttributeMaxDynamicSharedMemorySize, SMEM_BYTES);

    // 0) round all weights (one launch)
    round4_kernel<<<(4 * WELEMS / 4 + 255) / 256, 256>>>(
        w_theta, wth, w_phi, wph, w_g, wg, w_out, wout);

    // 1) x -> xT (transpose + round)
    transpose_kernel<<<dim3(THW / 32, CC / 32, NB), dim3(32, 8)>>>(x, xT);

    // 2) xT -> xpT (pooled transpose)
    pooltrans_kernel<<<dim3(PP, NB), 256>>>(xT, xpT);

    // 3) thetaT = xT · wth^T : M=3136 N=512 K=1024  (round out)
    mma_gemm<false, true><<<g128(THW, DD, NB), NT, SMEM_BYTES>>>(
        xT, wth, thetaT, THW, DD, CC,
        CC, CC, DD, (long long)THW * CC, 0LL, (long long)THW * DD,
        1.0f, nullptr, nullptr, nullptr, 0LL);

    // 4) phiT = xpT · wph^T : M=784 N=512 K=1024  (round out)
    mma_gemm<false, true><<<g128(PP, DD, NB), NT, SMEM_BYTES>>>(
        xpT, wph, phiT, PP, DD, CC,
        CC, CC, DD, (long long)PP * CC, 0LL, (long long)PP * DD,
        1.0f, nullptr, nullptr, nullptr, 0LL);

    // 5) g = wg · xpT^T : M=512 N=784 K=1024  (round out)
    mma_gemm<false, true><<<g128(DD, PP, NB), NT, SMEM_BYTES>>>(
        wg, xpT, gg, DD, PP, CC,
        CC, CC, PP, 0LL, (long long)PP * CC, (long long)DD * PP,
        1.0f, nullptr, nullptr, nullptr, 0LL);

    // 6) attn = thetaT · phiT^T * D^-0.5 : M=3136 N=784 K=512
    mma_gemm<false, false><<<g128(THW, PP, NB), NT, SMEM_BYTES>>>(
        thetaT, phiT, attn, THW, PP, DD,
        DD, DD, PP, (long long)THW * DD, (long long)PP * DD, (long long)THW * PP,
        0.044194173824159216f, nullptr, nullptr, nullptr, 0LL);

    // 7) softmax rows over 784 (rounds output)
    softmax_kernel<<<(NB * THW + 7) / 8, 256>>>(attn, NB * THW, PP);

    // 8) oT = attn · g^T : M=3136 N=512 K=784  (round out)
    mma_gemm<false, true><<<g128(THW, DD, NB), NT, SMEM_BYTES>>>(
        attn, gg, oT, THW, DD, PP,
        PP, PP, DD, (long long)THW * PP, (long long)DD * PP, (long long)THW * DD,
        1.0f, nullptr, nullptr, nullptr, 0LL);

    // 9) out = x + (wout · oT^T)*scale + bias : M=1024 N=3136 K=512
    mma_gemm<true, false><<<g128(CC, THW, NB), NT, SMEM_BYTES>>>(
        wout, oT, out, CC, THW, DD,
        DD, DD, THW, 0LL, (long long)THW * DD, (long long)CC * THW,
        1.0f, nscale, nbias, x, (long long)CC * THW);
}

// round 11
// speedup vs baseline: 1.9296x; 1.9296x over previous
#include <cuda_runtime.h>
#include <cuda_fp16.h>
#include <cstdint>
#include <math.h>

// ---------------------------------------------------------------------------
// Problem dims
// ---------------------------------------------------------------------------
#define NB   8
#define CC   1024
#define TT   16
#define HH   14
#define WW   14
#define DD   512
#define THW  (TT*HH*WW)   // 3136
#define PH   (HH/2)
#define PW   (WW/2)
#define PP   (TT*PH*PW)   // 784

// Scratch: fp16 K-contiguous operands, fp32 logits
__device__ __half h_xT    [NB*THW*CC];
__device__ __half h_xpT   [NB*PP*CC];
__device__ __half h_thetaT[NB*THW*DD];
__device__ __half h_phiT  [NB*PP*DD];
__device__ __half h_g     [NB*DD*PP];
__device__ float  g_attn  [NB*THW*PP];   // fp32 logits (softmax input)
__device__ __half h_attn  [NB*THW*PP];   // fp16 attn (softmax output)
__device__ __half h_oT    [NB*THW*DD];
__device__ __half h_wth   [DD*CC];
__device__ __half h_wph   [DD*CC];
__device__ __half h_wg    [DD*CC];
__device__ __half h_wout  [CC*DD];

// ---------------------------------------------------------------------------
// Tile geometry: 128x128 CTA tile, BK=64 (fp16), 256 threads, 8 warps 64x32,
// 2-stage cp.async pipeline (3-stage regressed in R10).
// ---------------------------------------------------------------------------
#define BM  128
#define BN  128
#define BK  64
#define NT  256
#define PADH 8
#define LDT (BK + PADH)         // 72 halfs = 144 B per row (16B-aligned)
#define TILE_HALFS ((BM + BN) * LDT)
#define SMEM_BYTES  (2 * TILE_HALFS * 2)   // 73728 B

// ---------------------------------------------------------------------------
// PTX helpers
// ---------------------------------------------------------------------------
__device__ __forceinline__ uint32_t smem_u32(const void* p) {
    uint32_t a;
    asm("{ .reg .u64 t; cvta.to.shared.u64 t, %1; cvt.u32.u64 %0, t; }" : "=r"(a) : "l"(p));
    return a;
}
__device__ __forceinline__ void cp16(uint32_t dst, const void* src, bool pred) {
    int sz = pred ? 16 : 0;
    asm volatile("cp.async.ca.shared.global [%0], [%1], 16, %2;"
                 :: "r"(dst), "l"(src), "r"(sz));
}
#define CP_COMMIT() asm volatile("cp.async.commit_group;" ::: "memory")
template<int N> __device__ __forceinline__ void cp_wait() {
    asm volatile("cp.async.wait_group %0;" :: "n"(N) : "memory");
}
__device__ __forceinline__ void mma16(float* c, const uint32_t* a, const uint32_t* b) {
    asm volatile(
        "mma.sync.aligned.m16n8k16.row.col.f32.f16.f16.f32 "
        "{%0,%1,%2,%3}, {%4,%5,%6,%7}, {%8,%9}, {%0,%1,%2,%3};"
        : "+f"(c[0]), "+f"(c[1]), "+f"(c[2]), "+f"(c[3])
        : "r"(a[0]), "r"(a[1]), "r"(a[2]), "r"(a[3]), "r"(b[0]), "r"(b[1]));
}
__device__ __forceinline__ void ldsm4(uint32_t* r, uint32_t addr) {
    asm volatile("ldmatrix.sync.aligned.m8n8.x4.shared.b16 {%0,%1,%2,%3}, [%4];"
                 : "=r"(r[0]), "=r"(r[1]), "=r"(r[2]), "=r"(r[3]) : "r"(addr));
}

// K-contiguous fp16 staging: elem(r,k)=src[r*ld+k]; 16B = 8 halfs per chunk.
// 256 threads x 4 iters = 1024 chunks = 128 rows x 8 chunks (64 halfs).
__device__ __forceinline__ void stage_kc(const __half* __restrict__ src, uint32_t tile_u,
                                         int rows, int k0, int K, long long ld, int tid) {
    #pragma unroll
    for (int i = 0; i < 4; i++) {
        int idx = tid + i * NT;
        int r   = idx >> 3;
        int c8  = (idx & 7) * 8;
        bool ok = (r < rows) && (k0 + c8 < K);
        const __half* s = ok ? (src + (long long)r * ld + k0 + c8) : src;
        cp16(tile_u + (uint32_t)(r * LDT + c8) * 2u, s, ok);
    }
}

// ---------------------------------------------------------------------------
// fp16 mma.sync GEMM (ldmatrix fragments): C = alpha * A·B^T, both operands
// K-contiguous fp16. 8 warps, 64x32 warp tile, 2-stage cp.async.
// MODE 0: half output (alpha applied); MODE 1: float output (alpha applied);
// MODE 2: float output, C = resid + acc*scale[m] + bias[m].
// ---------------------------------------------------------------------------
template<int MODE>
__global__ __launch_bounds__(NT, 2)
void mma_gemm(const __half* __restrict__ A, const __half* __restrict__ B,
              void* __restrict__ Cv, int M, int N, int K,
              long long ldA, long long ldB, long long ldC,
              long long sA, long long sB, long long sC, float alpha,
              const float* __restrict__ scale, const float* __restrict__ bias,
              const float* __restrict__ resid, long long sR) {
    extern __shared__ __half smem[];
    const int tid  = threadIdx.x;
    const int wid  = tid >> 5;
    const int lane = tid & 31;
    const int bz = blockIdx.z;
    const int bm = blockIdx.y * BM;
    const int bn = blockIdx.x * BN;

    A += (long long)bz * sA;
    B += (long long)bz * sB;

    const int rowsA = min(BM, M - bm);
    const int rowsB = min(BN, N - bn);
    const __half* srcA = A + (long long)bm * ldA;
    const __half* srcB = B + (long long)bn * ldB;

    const uint32_t smb = smem_u32(smem);
    const uint32_t uA[2] = { smb, smb + (uint32_t)TILE_HALFS * 2u };
    const uint32_t uB[2] = { smb + (uint32_t)(BM * LDT) * 2u,
                             smb + (uint32_t)(TILE_HALFS + BM * LDT) * 2u };

    const int wm = (wid >> 2) * 64;
    const int wn = (wid & 3) * 32;

    // ldmatrix lane offsets (in halfs, *2 for bytes):
    //   A x4 tiles order: {m0,k0},{m8,k0},{m0,k8},{m8,k8} -> a0..a3
    //   B x4 tiles order: {n0,k0},{n0,k8},{n8,k0},{n8,k8} -> b0,b1 of 2 n-tiles
    const int lrow = lane & 7, grp = lane >> 3;
    const uint32_t aoff = ((lrow + (grp & 1) * 8) * LDT + (grp >> 1) * 8) * 2u;
    const uint32_t boff = ((lrow + (grp >> 1) * 8) * LDT + (grp & 1) * 8) * 2u;

    float acc[4][4][4];
    #pragma unroll
    for (int i = 0; i < 4; i++)
        #pragma unroll
        for (int j = 0; j < 4; j++)
            #pragma unroll
            for (int e = 0; e < 4; e++) acc[i][j][e] = 0.f;

    const int KT = (K + BK - 1) / BK;

    // prologue
    stage_kc(srcA, uA[0], rowsA, 0, K, ldA, tid);
    stage_kc(srcB, uB[0], rowsB, 0, K, ldB, tid);
    CP_COMMIT();
    cp_wait<0>();
    __syncthreads();

    for (int kt = 0; kt < KT; kt++) {
        const int buf = kt & 1;
        const bool pf = (kt + 1 < KT);
        if (pf) {
            const int k0 = (kt + 1) * BK;
            stage_kc(srcA, uA[buf ^ 1], rowsA, k0, K, ldA, tid);
            stage_kc(srcB, uB[buf ^ 1], rowsB, k0, K, ldB, tid);
            CP_COMMIT();
        }

        const uint32_t abase = uA[buf] + (uint32_t)(wm * LDT) * 2u + aoff;
        const uint32_t bbase = uB[buf] + (uint32_t)(wn * LDT) * 2u + boff;
        #pragma unroll
        for (int ks = 0; ks < 4; ks++) {                 // 4 x k16 = BK=64
            const uint32_t ksb = (uint32_t)(ks * 16) * 2u;
            uint32_t afr[4][4], bfr[4][2];
            #pragma unroll
            for (int i = 0; i < 4; i++)
                ldsm4(afr[i], abase + (uint32_t)(i * 16 * LDT) * 2u + ksb);
            #pragma unroll
            for (int p = 0; p < 2; p++) {
                uint32_t bq[4];
                ldsm4(bq, bbase + (uint32_t)(p * 16 * LDT) * 2u + ksb);
                bfr[2 * p][0] = bq[0]; bfr[2 * p][1] = bq[1];
                bfr[2 * p + 1][0] = bq[2]; bfr[2 * p + 1][1] = bq[3];
            }
            #pragma unroll
            for (int i = 0; i < 4; i++)
                #pragma unroll
                for (int j = 0; j < 4; j++)
                    mma16(acc[i][j], afr[i], bfr[j]);
        }

        if (pf) cp_wait<0>();
        __syncthreads();
    }

    // epilogue
    #pragma unroll
    for (int i = 0; i < 4; i++) {
        const int r0 = bm + wm + i * 16 + (lane >> 2);
        #pragma unroll
        for (int j = 0; j < 4; j++) {
            const int c = bn + wn + j * 8 + 2 * (lane & 3);
            if (c >= N) continue;
            #pragma unroll
            for (int h = 0; h < 2; h++) {
                const int r = r0 + h * 8;
                if (r >= M) continue;
                const long long base = (long long)r * ldC + c;
                const float v0 = acc[i][j][2 * h + 0];
                const float v1 = acc[i][j][2 * h + 1];
                if (MODE == 0) {
                    __half* Ch = (__half*)Cv + (long long)bz * sC;
                    *reinterpret_cast<__half2*>(&Ch[base]) =
                        __floats2half2_rn(alpha * v0, alpha * v1);
                } else if (MODE == 1) {
                    float* Cf = (float*)Cv + (long long)bz * sC;
                    float2 o; o.x = alpha * v0; o.y = alpha * v1;
                    *reinterpret_cast<float2*>(&Cf[base]) = o;
                } else {
                    float* Cf = (float*)Cv + (long long)bz * sC;
                    const float sc = scale[r], bi = bias[r];
                    const float2 rr = *reinterpret_cast<const float2*>(
                        &resid[(long long)bz * sR + base]);
                    float2 o;
                    o.x = rr.x + fmaf(v0, sc, bi);
                    o.y = rr.y + fmaf(v1, sc, bi);
                    *reinterpret_cast<float2*>(&Cf[base]) = o;
                }
            }
        }
    }
}

// ---------------------------------------------------------------------------
// Weight conversion: float -> half, all four 512*1024 arrays in one launch.
// ---------------------------------------------------------------------------
#define WELEMS (DD*CC)
__global__ void cvt4_kernel(const float* __restrict__ s0, __half* __restrict__ d0,
                            const float* __restrict__ s1, __half* __restrict__ d1,
                            const float* __restrict__ s2, __half* __restrict__ d2,
                            const float* __restrict__ s3, __half* __restrict__ d3) {
    int gi = (blockIdx.x * blockDim.x + threadIdx.x) * 4;
    int arr = gi / WELEMS;
    int i   = gi % WELEMS;
    const float* src = (arr == 0) ? s0 : (arr == 1) ? s1 : (arr == 2) ? s2 : s3;
    __half*      dst = (arr == 0) ? d0 : (arr == 1) ? d1 : (arr == 2) ? d2 : d3;
    float4 v = *reinterpret_cast<const float4*>(src + i);
    __half2 lo = __floats2half2_rn(v.x, v.y);
    __half2 hi = __floats2half2_rn(v.z, v.w);
    *reinterpret_cast<__half2*>(dst + i)     = lo;
    *reinterpret_cast<__half2*>(dst + i + 2) = hi;
}

// ---------------------------------------------------------------------------
// Tiled transpose + fp16 convert: x [C, THW] -> xT [THW, C]
// ---------------------------------------------------------------------------
__global__ void transpose_kernel(const float* __restrict__ x, __half* __restrict__ xT) {
    __shared__ float tile[32][33];
    const int bz = blockIdx.z;
    const float* src = x  + (long long)bz * CC * THW;
    __half*      dst = xT + (long long)bz * THW * CC;
    const int t0 = blockIdx.x * 32;
    const int c0 = blockIdx.y * 32;
    #pragma unroll
    for (int j = threadIdx.y; j < 32; j += 8)
        tile[j][threadIdx.x] = src[(long long)(c0 + j) * THW + t0 + threadIdx.x];
    __syncthreads();
    #pragma unroll
    for (int j = threadIdx.y; j < 32; j += 8)
        dst[(long long)(t0 + j) * CC + c0 + threadIdx.x] = __float2half(tile[threadIdx.x][j]);
}

// ---------------------------------------------------------------------------
// Pooled transpose (fp16): xT [THW, C] -> xpT [PP, C], max over 2x2 window.
// ---------------------------------------------------------------------------
__global__ void pooltrans_kernel(const __half* __restrict__ xT, __half* __restrict__ xpT) {
    const int p  = blockIdx.x;
    const int nb = blockIdx.y;
    const int t  = p / (PH * PW);
    const int ij = p % (PH * PW);
    const int i  = ij / PW;
    const int j  = ij % PW;
    const int r00 = t * (HH * WW) + (2 * i) * WW + 2 * j;
    const __half2* s0 = (const __half2*)(xT + ((long long)nb * THW + r00) * CC);
    const __half2* s1 = s0 + CC / 2;                       // r00 + 1
    const __half2* s2 = (const __half2*)(xT + ((long long)nb * THW + r00 + WW) * CC);
    const __half2* s3 = s2 + CC / 2;                       // r00 + WW + 1
    __half2* d = (__half2*)(xpT + ((long long)nb * PP + p) * CC);
    #pragma unroll
    for (int it = 0; it < 2; it++) {
        const int c = threadIdx.x + it * 256;              // 512 half2 = 1024 halfs
        d[c] = __hmax2(__hmax2(s0[c], s1[c]), __hmax2(s2[c], s3[c]));
    }
}

// ---------------------------------------------------------------------------
// Warp-per-row softmax over 784 fp32 logits; writes fp16 attn.
// ---------------------------------------------------------------------------
__global__ void softmax_kernel(const float* __restrict__ logits,
                               __half* __restrict__ attn, int rows, int cols) {
    int warp = blockIdx.x * (blockDim.x >> 5) + (threadIdx.x >> 5);
    if (warp >= rows) return;
    int lane = threadIdx.x & 31;
    const float* row = logits + (long long)warp * cols;
    __half*      orow = attn  + (long long)warp * cols;
    float vals[25];
    int cnt = 0;
    float mx = -INFINITY;
    for (int c = lane; c < cols; c += 32) {
        float v = row[c];
        vals[cnt++] = v;
        mx = fmaxf(mx, v);
    }
    #pragma unroll
    for (int o = 16; o; o >>= 1) mx = fmaxf(mx, __shfl_xor_sync(0xffffffffu, mx, o));
    float sum = 0.f;
    for (int i = 0; i < cnt; i++) { vals[i] = __expf(vals[i] - mx); sum += vals[i]; }
    #pragma unroll
    for (int o = 16; o; o >>= 1) sum += __shfl_xor_sync(0xffffffffu, sum, o);
    float inv = 1.0f / sum;
    cnt = 0;
    for (int c = lane; c < cols; c += 32) orow[c] = __float2half(vals[cnt++] * inv);
}

// ---------------------------------------------------------------------------
// Launch
// ---------------------------------------------------------------------------
static inline dim3 g128(int M, int N, int b) {
    return dim3((N + BN - 1) / BN, (M + BM - 1) / BM, b);
}

extern "C" void kernel_launch(void* const* d_in, const int* in_sizes, int n_in,
                              void* d_out, int out_size) {
    const float* x       = (const float*)d_in[0];
    const float* w_theta = (const float*)d_in[1];
    const float* w_phi   = (const float*)d_in[2];
    const float* w_g     = (const float*)d_in[3];
    const float* w_out   = (const float*)d_in[4];
    const float* nscale  = (const float*)d_in[5];
    const float* nbias   = (const float*)d_in[6];
    float* out = (float*)d_out;

    __half *xT, *xpT, *thetaT, *phiT, *gg, *attnH, *oT, *wth, *wph, *wg, *wout;
    float  *attnF;
    cudaGetSymbolAddress((void**)&xT,     h_xT);
    cudaGetSymbolAddress((void**)&xpT,    h_xpT);
    cudaGetSymbolAddress((void**)&thetaT, h_thetaT);
    cudaGetSymbolAddress((void**)&phiT,   h_phiT);
    cudaGetSymbolAddress((void**)&gg,     h_g);
    cudaGetSymbolAddress((void**)&attnF,  g_attn);
    cudaGetSymbolAddress((void**)&attnH,  h_attn);
    cudaGetSymbolAddress((void**)&oT,     h_oT);
    cudaGetSymbolAddress((void**)&wth,    h_wth);
    cudaGetSymbolAddress((void**)&wph,    h_wph);
    cudaGetSymbolAddress((void**)&wg,     h_wg);
    cudaGetSymbolAddress((void**)&wout,   h_wout);

    cudaFuncSetAttribute(mma_gemm<0>, cudaFuncAttributeMaxDynamicSharedMemorySize, SMEM_BYTES);
    cudaFuncSetAttribute(mma_gemm<1>, cudaFuncAttributeMaxDynamicSharedMemorySize, SMEM_BYTES);
    cudaFuncSetAttribute(mma_gemm<2>, cudaFuncAttributeMaxDynamicSharedMemorySize, SMEM_BYTES);

    // 0) weights -> fp16
    cvt4_kernel<<<(4 * WELEMS / 4 + 255) / 256, 256>>>(
        w_theta, wth, w_phi, wph, w_g, wg, w_out, wout);

    // 1) x -> xT (transpose + fp16)
    transpose_kernel<<<dim3(THW / 32, CC / 32, NB), dim3(32, 8)>>>(x, xT);

    // 2) xT -> xpT (pooled transpose)
    pooltrans_kernel<<<dim3(PP, NB), 256>>>(xT, xpT);

    // 3) thetaT = xT · wth^T : M=3136 N=512 K=1024 -> half
    mma_gemm<0><<<g128(THW, DD, NB), NT, SMEM_BYTES>>>(
        xT, wth, thetaT, THW, DD, CC,
        CC, CC, DD, (long long)THW * CC, 0LL, (long long)THW * DD,
        1.0f, nullptr, nullptr, nullptr, 0LL);

    // 4) phiT = xpT · wph^T : M=784 N=512 K=1024 -> half
    mma_gemm<0><<<g128(PP, DD, NB), NT, SMEM_BYTES>>>(
        xpT, wph, phiT, PP, DD, CC,
        CC, CC, DD, (long long)PP * CC, 0LL, (long long)PP * DD,
        1.0f, nullptr, nullptr, nullptr, 0LL);

    // 5) g = wg · xpT^T : M=512 N=784 K=1024 -> half
    mma_gemm<0><<<g128(DD, PP, NB), NT, SMEM_BYTES>>>(
        wg, xpT, gg, DD, PP, CC,
        CC, CC, PP, 0LL, (long long)PP * CC, (long long)DD * PP,
        1.0f, nullptr, nullptr, nullptr, 0LL);

    // 6) logits = thetaT · phiT^T * D^-0.5 : M=3136 N=784 K=512 -> float
    mma_gemm<1><<<g128(THW, PP, NB), NT, SMEM_BYTES>>>(
        thetaT, phiT, attnF, THW, PP, DD,
        DD, DD, PP, (long long)THW * DD, (long long)PP * DD, (long long)THW * PP,
        0.044194173824159216f, nullptr, nullptr, nullptr, 0LL);

    // 7) softmax fp32 -> fp16
    softmax_kernel<<<(NB * THW + 7) / 8, 256>>>(attnF, attnH, NB * THW, PP);

    // 8) oT = attnH · g^T : M=3136 N=512 K=784 -> half
    mma_gemm<0><<<g128(THW, DD, NB), NT, SMEM_BYTES>>>(
        attnH, gg, oT, THW, DD, PP,
        PP, PP, DD, (long long)THW * PP, (long long)DD * PP, (long long)THW * DD,
        1.0f, nullptr, nullptr, nullptr, 0LL);

    // 9) out = x + (wout · oT^T)*scale + bias : M=1024 N=3136 K=512 -> float+EPI
    mma_gemm<2><<<g128(CC, THW, NB), NT, SMEM_BYTES>>>(
        wout, oT, out, CC, THW, DD,
        DD, DD, THW, 0LL, (long long)THW * DD, (long long)CC * THW,
        1.0f, nscale, nbias, x, (long long)CC * THW);
}